// round 2
// baseline (speedup 1.0000x reference)
#include <cuda_runtime.h>
#include <math.h>

#define C 96
#define FOURC 384
#define NNODES 4096
#define TILE 32
#define NTHREADS 256
#define NCTAS (NNODES / TILE)   // 128

// ---------------- shared memory layout (floats) ----------------
#define OFF_A    0        // 12288: nf tile, later out tile (32 x 384)
#define OFF_B    12288    // 9216 : staged weight matrix (96 x 96) / MLP weights
#define OFF_X0   21504    // 3072 : x0 (32 x 96)
#define OFF_X1   24576    // 9216 : x1 [m][n][u] (3 x 32 x 96)
#define OFF_Q    33792    // 3072 : q  (32 x 96)
#define OFF_F    36864    // 3072 : norms, later s_a (32 x 96)
#define OFF_G    39936    // 12288: tp_w (32 x 384)
#define OFF_H1   52224    // 512  : MLP hidden (32 x 16)
#define OFF_H2   52736    // 512
#define OFF_POT  53248    // 128  : pot tile (32 x 4)
#define SMEM_FLOATS 53376
#define SMEM_BYTES (SMEM_FLOATS * 4)

// ---------------- device scratch (precomputed, no allocations) ----------------
__device__ __align__(16) float g_G0[C * C];
__device__ __align__(16) float g_G1[C * C];
__device__ __align__(16) float g_G2[C * C];
__device__ float g_silu_cst;

// ---------------------------------------------------------------------------
// Precompute kernel: collapse the C x C x C fctp tensors against the rank-1
// y-factors into three C x C matrices, and compute SILU_CST by replicating
// the reference quadrature.
// ---------------------------------------------------------------------------
__global__ void precompute_kernel(const float* __restrict__ W00,
                                  const float* __restrict__ W11,
                                  const float* __restrict__ Wl2_0,
                                  const float* __restrict__ bl2_0,
                                  const float* __restrict__ Wl2_1)
{
    if (blockIdx.x < 36) {
        int idx = blockIdx.x * 256 + threadIdx.x;   // (u, w) pair, w fastest
        int u = idx / C;
        int w = idx - u * C;
        const float* p00 = W00 + u * C * C + w;
        const float* p11 = W11 + u * C * C + w;
        float a = 0.f, b = 0.f, c = 0.f;
        #pragma unroll 4
        for (int v = 0; v < C; v++) {
            float e00 = p00[v * C];
            float e11 = p11[v * C];
            a = fmaf(Wl2_0[v], e00, a);
            b = fmaf(bl2_0[v], e00, b);
            c = fmaf(Wl2_1[v], e11, c);
        }
        const float inv_s2 = 1.0f / sqrtf(2.0f * C * C);     // product scale
        const float inv_s3 = 1.0f / sqrtf(3.0f);
        g_G0[idx] = a * inv_s2;
        g_G1[idx] = b * inv_s2;
        g_G2[idx] = c * inv_s2 * inv_s3;
    } else {
        // SILU_CST = 1/sqrt( sum s(z)^2 pdf(z) dz ), z in linspace(-12,12,200001)
        __shared__ double partial[256];
        const double dz = 24.0 / 200000.0;
        double local = 0.0;
        for (int i = threadIdx.x; i <= 200000; i += 256) {
            float z = (float)(-12.0 + i * dz);
            float s = z / (1.0f + expf(-z));
            float pdf = expf(-0.5f * z * z) * 0.3989422804014327f;
            local += (double)(s * s * pdf);
        }
        partial[threadIdx.x] = local;
        __syncthreads();
        for (int off = 128; off > 0; off >>= 1) {
            if (threadIdx.x < off) partial[threadIdx.x] += partial[threadIdx.x + off];
            __syncthreads();
        }
        if (threadIdx.x == 0)
            g_silu_cst = (float)(1.0 / sqrt(partial[0] * dz));
    }
}

// ---------------------------------------------------------------------------
// Main fused kernel helpers
// ---------------------------------------------------------------------------
__device__ __forceinline__ void stageW4(float* dst, const float* __restrict__ src, int n4)
{
    float4* d = reinterpret_cast<float4*>(dst);
    const float4* s = reinterpret_cast<const float4*>(src);
    for (int i = threadIdx.x; i < n4; i += NTHREADS) d[i] = s[i];
}

__device__ __forceinline__ void loadw12(float w[12], const float* wrow)
{
    *reinterpret_cast<float4*>(w)     = *reinterpret_cast<const float4*>(wrow);
    *reinterpret_cast<float4*>(w + 4) = *reinterpret_cast<const float4*>(wrow + 4);
    *reinterpret_cast<float4*>(w + 8) = *reinterpret_cast<const float4*>(wrow + 8);
}

__device__ __forceinline__ void fma12(float acc[12], float a, const float* wrow)
{
    float w[12];
    loadw12(w, wrow);
    #pragma unroll
    for (int j = 0; j < 12; j++) acc[j] = fmaf(a, w[j], acc[j]);
}

__device__ __forceinline__ void fma12x3(float a0c[12], float a1c[12], float a2c[12],
                                        float b0, float b1, float b2, const float* wrow)
{
    float w[12];
    loadw12(w, wrow);
    #pragma unroll
    for (int j = 0; j < 12; j++) {
        a0c[j] = fmaf(b0, w[j], a0c[j]);
        a1c[j] = fmaf(b1, w[j], a1c[j]);
        a2c[j] = fmaf(b2, w[j], a2c[j]);
    }
}

// ---------------------------------------------------------------------------
// Fused main kernel: 1 CTA = 32 nodes, full pipeline in shared memory.
// Thread mapping for all 96-col GEMMs: n = tid>>3 (node), v0 = (tid&7)*12.
// ---------------------------------------------------------------------------
__global__ void __launch_bounds__(NTHREADS, 1)
main_kernel(const float* __restrict__ nf, const float* __restrict__ pot,
            const float* __restrict__ Wl1_0, const float* __restrict__ Wl1_1,
            const float* __restrict__ Wm1, const float* __restrict__ Wm2,
            const float* __restrict__ Wm3, const float* __restrict__ Wm4,
            const float* __restrict__ Wo0a, const float* __restrict__ Wo0b,
            const float* __restrict__ Wo1a, const float* __restrict__ Wo1b,
            float* __restrict__ out)
{
    extern __shared__ __align__(16) float sm[];
    float* A   = sm + OFF_A;
    float* B   = sm + OFF_B;
    float* X0  = sm + OFF_X0;
    float* X1  = sm + OFF_X1;
    float* Q   = sm + OFF_Q;
    float* F   = sm + OFF_F;
    float* G   = sm + OFF_G;
    float* H1  = sm + OFF_H1;
    float* H2  = sm + OFF_H2;
    float* POT = sm + OFF_POT;

    const float INV_SQRTC = 1.0f / sqrtf((float)C);
    const float INV_SQRT3 = 1.0f / sqrtf(3.0f);
    const float NORM_OUT  = 1.0f / sqrtf(2.0f * C);

    const int tid = threadIdx.x;
    const int nb  = blockIdx.x * TILE;
    const int n   = tid >> 3;
    const int v0  = (tid & 7) * 12;

    // ---- load node_feats tile + pot tile, stage W_l1_0 ----
    {
        const float4* src = reinterpret_cast<const float4*>(nf + (size_t)nb * FOURC);
        float4* dst = reinterpret_cast<float4*>(A);
        for (int i = tid; i < TILE * FOURC / 4; i += NTHREADS) dst[i] = src[i];
    }
    if (tid < TILE * 4) POT[tid] = pot[nb * 4 + tid];
    stageW4(B, Wl1_0, C * C / 4);
    __syncthreads();

    // ---- stage 1: x0 = nf[:, :C] @ W_l1_0 * invC ----
    {
        float acc[12];
        #pragma unroll
        for (int j = 0; j < 12; j++) acc[j] = 0.f;
        const float* arow = A + n * FOURC;
        #pragma unroll 8
        for (int u = 0; u < C; u++) fma12(acc, arow[u], B + u * C + v0);
        float* x0r = X0 + n * C + v0;
        #pragma unroll
        for (int j = 0; j < 12; j++) x0r[j] = acc[j] * INV_SQRTC;
    }
    __syncthreads();

    // ---- stage 2: x1_m = nf1_m @ W_l1_1 * invC, and q = sum_m x1_m * p1_m ----
    stageW4(B, Wl1_1, C * C / 4);
    __syncthreads();
    {
        float c0[12], c1[12], c2[12];
        #pragma unroll
        for (int j = 0; j < 12; j++) { c0[j] = 0.f; c1[j] = 0.f; c2[j] = 0.f; }
        const float* arow = A + n * FOURC + C;   // (u, m) at arow[u*3+m]
        #pragma unroll 4
        for (int u = 0; u < C; u++)
            fma12x3(c0, c1, c2, arow[u * 3], arow[u * 3 + 1], arow[u * 3 + 2], B + u * C + v0);
        float p10 = POT[n * 4 + 1], p11v = POT[n * 4 + 2], p12 = POT[n * 4 + 3];
        float* x1r0 = X1 + 0 * (TILE * C) + n * C + v0;
        float* x1r1 = X1 + 1 * (TILE * C) + n * C + v0;
        float* x1r2 = X1 + 2 * (TILE * C) + n * C + v0;
        float* qr   = Q + n * C + v0;
        #pragma unroll
        for (int j = 0; j < 12; j++) {
            float e0 = c0[j] * INV_SQRTC, e1 = c1[j] * INV_SQRTC, e2 = c2[j] * INV_SQRTC;
            x1r0[j] = e0; x1r1[j] = e1; x1r2[j] = e2;
            qr[j] = e0 * p10 + e1 * p11v + e2 * p12;
        }
    }
    __syncthreads();

    // ---- stage 3: product = p0*(x0@G0) + x0@G1 + q@G2 ; norms = product^2 ----
    float accZ[12];
    {
        const float p0 = POT[n * 4 + 0];
        const float* x0r = X0 + n * C;
        const float* qr  = Q + n * C;
        float t[12];

        stageW4(B, g_G0, C * C / 4);
        __syncthreads();
        #pragma unroll
        for (int j = 0; j < 12; j++) t[j] = 0.f;
        #pragma unroll 8
        for (int u = 0; u < C; u++) fma12(t, x0r[u], B + u * C + v0);
        #pragma unroll
        for (int j = 0; j < 12; j++) accZ[j] = p0 * t[j];
        __syncthreads();

        stageW4(B, g_G1, C * C / 4);
        __syncthreads();
        #pragma unroll
        for (int j = 0; j < 12; j++) t[j] = 0.f;
        #pragma unroll 8
        for (int u = 0; u < C; u++) fma12(t, x0r[u], B + u * C + v0);
        #pragma unroll
        for (int j = 0; j < 12; j++) accZ[j] += t[j];
        __syncthreads();

        stageW4(B, g_G2, C * C / 4);
        __syncthreads();
        #pragma unroll
        for (int j = 0; j < 12; j++) t[j] = 0.f;
        #pragma unroll 8
        for (int u = 0; u < C; u++) fma12(t, qr[u], B + u * C + v0);
        float* fr = F + n * C + v0;
        #pragma unroll
        for (int j = 0; j < 12; j++) {
            float pr = accZ[j] + t[j];
            fr[j] = pr * pr;
        }
    }
    __syncthreads();

    // ---- stage 4: MLP norms -> tp_w ----
    stageW4(B,        Wm1, (C * 16) / 4);      // 96x16 at B[0]
    stageW4(B + 1536, Wm2, (16 * 16) / 4);     // 16x16
    stageW4(B + 1792, Wm3, (16 * 16) / 4);     // 16x16
    stageW4(B + 2048, Wm4, (16 * FOURC) / 4);  // 16x384
    __syncthreads();
    {
        const float cst = g_silu_cst;
        // h1
        for (int idx = tid; idx < TILE * 16; idx += NTHREADS) {
            int nn = idx >> 4, j = idx & 15;
            const float* nr = F + nn * C;
            float s = 0.f;
            #pragma unroll 8
            for (int u = 0; u < C; u++) s = fmaf(nr[u], B[u * 16 + j], s);
            s *= INV_SQRTC;
            H1[idx] = cst * s / (1.0f + expf(-s));
        }
        __syncthreads();
        // h2
        for (int idx = tid; idx < TILE * 16; idx += NTHREADS) {
            int nn = idx >> 4, j = idx & 15;
            float s = 0.f;
            #pragma unroll
            for (int k = 0; k < 16; k++) s = fmaf(H1[nn * 16 + k], B[1536 + k * 16 + j], s);
            s *= 0.25f;
            H2[idx] = cst * s / (1.0f + expf(-s));
        }
        __syncthreads();
        // h3
        for (int idx = tid; idx < TILE * 16; idx += NTHREADS) {
            int nn = idx >> 4, j = idx & 15;
            float s = 0.f;
            #pragma unroll
            for (int k = 0; k < 16; k++) s = fmaf(H2[nn * 16 + k], B[1792 + k * 16 + j], s);
            s *= 0.25f;
            H1[idx] = cst * s / (1.0f + expf(-s));
        }
        __syncthreads();
        // tp_w = h3 @ W_mlp4 * 0.25  -> G (32 x 384)
        for (int idx = tid; idx < TILE * FOURC; idx += NTHREADS) {
            int nn = idx / FOURC, j = idx - nn * FOURC;
            float s = 0.f;
            #pragma unroll
            for (int k = 0; k < 16; k++) s = fmaf(H1[nn * 16 + k], B[2048 + k * FOURC + j], s);
            G[idx] = s * 0.25f;
        }
    }
    __syncthreads();

    // ---- stage 5: outputs ----
    const float p0  = POT[n * 4 + 0];
    const float p10 = POT[n * 4 + 1], p11v = POT[n * 4 + 2], p12 = POT[n * 4 + 3];
    const float* tpr = G + n * FOURC;   // [w00 | w01 | w10 | w11]
    const float* x0r = X0 + n * C;
    const float* qr  = Q + n * C;

    // s_a = (w01*x0) @ W_out1a  -> F (norms are dead)
    stageW4(B, Wo1a, C * C / 4);
    __syncthreads();
    {
        float t[12];
        #pragma unroll
        for (int j = 0; j < 12; j++) t[j] = 0.f;
        #pragma unroll 4
        for (int u = 0; u < C; u++) fma12(t, tpr[C + u] * x0r[u], B + u * C + v0);
        float* fr = F + n * C + v0;
        #pragma unroll
        for (int j = 0; j < 12; j++) fr[j] = t[j];
    }
    __syncthreads();

    // s_b_m = (w10*x1_m) @ W_out1b ; out1[n,v,m] = (p1m*s_a + p0*s_b_m)*norm_out
    stageW4(B, Wo1b, C * C / 4);
    __syncthreads();
    {
        float c0[12], c1[12], c2[12];
        #pragma unroll
        for (int j = 0; j < 12; j++) { c0[j] = 0.f; c1[j] = 0.f; c2[j] = 0.f; }
        const float* x1r0 = X1 + 0 * (TILE * C) + n * C;
        const float* x1r1 = X1 + 1 * (TILE * C) + n * C;
        const float* x1r2 = X1 + 2 * (TILE * C) + n * C;
        #pragma unroll 4
        for (int u = 0; u < C; u++) {
            float w10v = tpr[2 * C + u];
            fma12x3(c0, c1, c2, w10v * x1r0[u], w10v * x1r1[u], w10v * x1r2[u], B + u * C + v0);
        }
        const float* sar = F + n * C + v0;
        float* outr = A + n * FOURC + C;   // out1 part of the output row
        #pragma unroll
        for (int j = 0; j < 12; j++) {
            float sa = sar[j];
            int v = v0 + j;
            outr[v * 3 + 0] = (p10 * sa + p0 * c0[j]) * NORM_OUT;
            outr[v * 3 + 1] = (p11v * sa + p0 * c1[j]) * NORM_OUT;
            outr[v * 3 + 2] = (p12 * sa + p0 * c2[j]) * NORM_OUT;
        }
    }
    __syncthreads();

    // out0 = ( p0*((w00*x0)@W_out0a) + inv_sqrt3*((w11*q)@W_out0b) ) * norm_out
    stageW4(B, Wo0a, C * C / 4);
    __syncthreads();
    float o1[12];
    {
        #pragma unroll
        for (int j = 0; j < 12; j++) o1[j] = 0.f;
        #pragma unroll 4
        for (int u = 0; u < C; u++) fma12(o1, tpr[u] * x0r[u], B + u * C + v0);
    }
    __syncthreads();
    stageW4(B, Wo0b, C * C / 4);
    __syncthreads();
    {
        float o2[12];
        #pragma unroll
        for (int j = 0; j < 12; j++) o2[j] = 0.f;
        #pragma unroll 4
        for (int u = 0; u < C; u++) fma12(o2, tpr[3 * C + u] * qr[u], B + u * C + v0);
        float* outr = A + n * FOURC;
        #pragma unroll
        for (int j = 0; j < 12; j++)
            outr[v0 + j] = (p0 * o1[j] + o2[j] * INV_SQRT3) * NORM_OUT;
    }
    __syncthreads();

    // ---- write output tile ----
    {
        float4* dst = reinterpret_cast<float4*>(out + (size_t)nb * FOURC);
        const float4* src = reinterpret_cast<const float4*>(A);
        for (int i = tid; i < TILE * FOURC / 4; i += NTHREADS) dst[i] = src[i];
    }
}

// ---------------------------------------------------------------------------
extern "C" void kernel_launch(void* const* d_in, const int* in_sizes, int n_in,
                              void* d_out, int out_size)
{
    const float* nf    = (const float*)d_in[0];
    const float* pot   = (const float*)d_in[1];
    const float* Wl1_0 = (const float*)d_in[2];
    const float* Wl1_1 = (const float*)d_in[3];
    const float* Wl2_0 = (const float*)d_in[4];
    const float* bl2_0 = (const float*)d_in[5];
    const float* Wl2_1 = (const float*)d_in[6];
    const float* W00   = (const float*)d_in[7];
    const float* W11   = (const float*)d_in[8];
    const float* Wm1   = (const float*)d_in[9];
    const float* Wm2   = (const float*)d_in[10];
    const float* Wm3   = (const float*)d_in[11];
    const float* Wm4   = (const float*)d_in[12];
    const float* Wo0a  = (const float*)d_in[13];
    const float* Wo0b  = (const float*)d_in[14];
    const float* Wo1a  = (const float*)d_in[15];
    const float* Wo1b  = (const float*)d_in[16];
    float* out = (float*)d_out;

    cudaFuncSetAttribute(main_kernel, cudaFuncAttributeMaxDynamicSharedMemorySize, SMEM_BYTES);

    precompute_kernel<<<37, 256>>>(W00, W11, Wl2_0, bl2_0, Wl2_1);
    main_kernel<<<NCTAS, NTHREADS, SMEM_BYTES>>>(nf, pot, Wl1_0, Wl1_1,
                                                 Wm1, Wm2, Wm3, Wm4,
                                                 Wo0a, Wo0b, Wo1a, Wo1b, out);
}

// round 3
// speedup vs baseline: 1.5649x; 1.5649x over previous
#include <cuda_runtime.h>
#include <math.h>

#define C 96
#define FOURC 384
#define NNODES 4096
#define TILE 16
#define NTHREADS 128
#define NCTAS (NNODES / TILE)   // 256

// ---------------- shared memory layout (floats) ----------------
#define OFF_B    0        // 9216 : staged weight matrix (96x96) / MLP weights
#define OFF_X0   9216     // 1536 : x0 (16 x 96)
#define OFF_X1   10752    // 4608 : x1 [m][n][u] (3 x 16 x 96)
#define OFF_Q    15360    // 1536 : q  (16 x 96)
#define OFF_F    16896    // 1536 : norms (16 x 96)
#define OFF_G    18432    // 6144 : tp_w (16 x 384)
#define OFF_H1   24576    // 256  : MLP hidden (16 x 16)
#define OFF_H2   24832    // 256
#define OFF_POT  25088    // 64   : pot tile (16 x 4)
#define SMEM_FLOATS 25152
#define SMEM_BYTES (SMEM_FLOATS * 4)   // 100608 -> 2 CTAs/SM

// ---------------- device scratch (precomputed, no allocations) ----------------
__device__ __align__(16) float g_G0[C * C];
__device__ __align__(16) float g_G1[C * C];
__device__ __align__(16) float g_G2[C * C];

// ---------------------------------------------------------------------------
// Precompute kernel: collapse the C x C x C fctp tensors against the rank-1
// y-factors into three C x C matrices (scales baked in).
// ---------------------------------------------------------------------------
__global__ void precompute_kernel(const float* __restrict__ W00,
                                  const float* __restrict__ W11,
                                  const float* __restrict__ Wl2_0,
                                  const float* __restrict__ bl2_0,
                                  const float* __restrict__ Wl2_1)
{
    int idx = blockIdx.x * 256 + threadIdx.x;   // (u, w) pair, w fastest
    if (idx >= C * C) return;
    int u = idx / C;
    int w = idx - u * C;
    const float* p00 = W00 + u * C * C + w;
    const float* p11 = W11 + u * C * C + w;
    float a = 0.f, b = 0.f, c = 0.f;
    #pragma unroll 4
    for (int v = 0; v < C; v++) {
        float e00 = p00[v * C];
        float e11 = p11[v * C];
        a = fmaf(Wl2_0[v], e00, a);
        b = fmaf(bl2_0[v], e00, b);
        c = fmaf(Wl2_1[v], e11, c);
    }
    const float inv_s2 = 1.0f / sqrtf(2.0f * C * C);     // product scale
    const float inv_s3 = 1.0f / sqrtf(3.0f);
    g_G0[idx] = a * inv_s2;
    g_G1[idx] = b * inv_s2;
    g_G2[idx] = c * inv_s2 * inv_s3;
}

// ---------------------------------------------------------------------------
// Main fused kernel helpers
// ---------------------------------------------------------------------------
__device__ __forceinline__ void stageW4(float* dst, const float* __restrict__ src, int n4)
{
    float4* d = reinterpret_cast<float4*>(dst);
    const float4* s = reinterpret_cast<const float4*>(src);
    for (int i = threadIdx.x; i < n4; i += NTHREADS) d[i] = s[i];
}

__device__ __forceinline__ void loadw12(float w[12], const float* wrow)
{
    *reinterpret_cast<float4*>(w)     = *reinterpret_cast<const float4*>(wrow);
    *reinterpret_cast<float4*>(w + 4) = *reinterpret_cast<const float4*>(wrow + 4);
    *reinterpret_cast<float4*>(w + 8) = *reinterpret_cast<const float4*>(wrow + 8);
}

__device__ __forceinline__ void fma12(float acc[12], float a, const float* wrow)
{
    float w[12];
    loadw12(w, wrow);
    #pragma unroll
    for (int j = 0; j < 12; j++) acc[j] = fmaf(a, w[j], acc[j]);
}

__device__ __forceinline__ void fma12x3(float a0c[12], float a1c[12], float a2c[12],
                                        float b0, float b1, float b2, const float* wrow)
{
    float w[12];
    loadw12(w, wrow);
    #pragma unroll
    for (int j = 0; j < 12; j++) {
        a0c[j] = fmaf(b0, w[j], a0c[j]);
        a1c[j] = fmaf(b1, w[j], a1c[j]);
        a2c[j] = fmaf(b2, w[j], a2c[j]);
    }
}

// ---------------------------------------------------------------------------
// Fused main kernel: 1 CTA = 16 nodes, full pipeline in shared memory.
// Thread mapping for all 96-col GEMMs: n = tid>>3 (node), v0 = (tid&7)*12.
// ---------------------------------------------------------------------------
__global__ void __launch_bounds__(NTHREADS, 2)
main_kernel(const float* __restrict__ nf, const float* __restrict__ pot,
            const float* __restrict__ Wl1_0, const float* __restrict__ Wl1_1,
            const float* __restrict__ Wm1, const float* __restrict__ Wm2,
            const float* __restrict__ Wm3, const float* __restrict__ Wm4,
            const float* __restrict__ Wo0a, const float* __restrict__ Wo0b,
            const float* __restrict__ Wo1a, const float* __restrict__ Wo1b,
            float* __restrict__ out, float silu_cst)
{
    extern __shared__ __align__(16) float sm[];
    float* B   = sm + OFF_B;
    float* X0  = sm + OFF_X0;
    float* X1  = sm + OFF_X1;
    float* Q   = sm + OFF_Q;
    float* F   = sm + OFF_F;
    float* G   = sm + OFF_G;
    float* H1  = sm + OFF_H1;
    float* H2  = sm + OFF_H2;
    float* POT = sm + OFF_POT;

    const float INV_SQRTC = 1.0f / sqrtf((float)C);
    const float INV_SQRT3 = 1.0f / sqrtf(3.0f);
    const float NORM_OUT  = 1.0f / sqrtf(2.0f * C);

    const int tid = threadIdx.x;
    const int nb  = blockIdx.x * TILE;
    const int n   = tid >> 3;
    const int v0  = (tid & 7) * 12;
    const int row = nb + n;

    // ---- load pot tile, stage W_l1_0 ----
    if (tid < TILE * 4) POT[tid] = pot[nb * 4 + tid];
    stageW4(B, Wl1_0, C * C / 4);
    __syncthreads();

    // ---- stage 1: x0 = nf[:, :C] @ W_l1_0 * invC (A-rows read from gmem/L1) ----
    {
        float acc[12];
        #pragma unroll
        for (int j = 0; j < 12; j++) acc[j] = 0.f;
        const float* arow = nf + (size_t)row * FOURC;
        #pragma unroll 2
        for (int u = 0; u < C; u += 4) {
            float4 a4 = *reinterpret_cast<const float4*>(arow + u);
            fma12(acc, a4.x, B + (u + 0) * C + v0);
            fma12(acc, a4.y, B + (u + 1) * C + v0);
            fma12(acc, a4.z, B + (u + 2) * C + v0);
            fma12(acc, a4.w, B + (u + 3) * C + v0);
        }
        float* x0r = X0 + n * C + v0;
        #pragma unroll
        for (int j = 0; j < 12; j++) x0r[j] = acc[j] * INV_SQRTC;
    }
    __syncthreads();

    // ---- stage 2: x1_m = nf1_m @ W_l1_1 * invC ; q = sum_m x1_m * p1_m ----
    stageW4(B, Wl1_1, C * C / 4);
    __syncthreads();
    {
        float c0[12], c1[12], c2[12];
        #pragma unroll
        for (int j = 0; j < 12; j++) { c0[j] = 0.f; c1[j] = 0.f; c2[j] = 0.f; }
        const float* arow = nf + (size_t)row * FOURC + C;   // (u, m) at arow[u*3+m]
        for (int u = 0; u < C; u += 4) {
            float4 b0 = *reinterpret_cast<const float4*>(arow + u * 3);
            float4 b1 = *reinterpret_cast<const float4*>(arow + u * 3 + 4);
            float4 b2 = *reinterpret_cast<const float4*>(arow + u * 3 + 8);
            fma12x3(c0, c1, c2, b0.x, b0.y, b0.z, B + (u + 0) * C + v0);
            fma12x3(c0, c1, c2, b0.w, b1.x, b1.y, B + (u + 1) * C + v0);
            fma12x3(c0, c1, c2, b1.z, b1.w, b2.x, B + (u + 2) * C + v0);
            fma12x3(c0, c1, c2, b2.y, b2.z, b2.w, B + (u + 3) * C + v0);
        }
        float p10 = POT[n * 4 + 1], p11v = POT[n * 4 + 2], p12 = POT[n * 4 + 3];
        float* x1r0 = X1 + 0 * (TILE * C) + n * C + v0;
        float* x1r1 = X1 + 1 * (TILE * C) + n * C + v0;
        float* x1r2 = X1 + 2 * (TILE * C) + n * C + v0;
        float* qr   = Q + n * C + v0;
        #pragma unroll
        for (int j = 0; j < 12; j++) {
            float e0 = c0[j] * INV_SQRTC, e1 = c1[j] * INV_SQRTC, e2 = c2[j] * INV_SQRTC;
            x1r0[j] = e0; x1r1[j] = e1; x1r2[j] = e2;
            qr[j] = e0 * p10 + e1 * p11v + e2 * p12;
        }
    }
    __syncthreads();

    // ---- stage 3: product = p0*(x0@G0) + x0@G1 + q@G2 ; norms = product^2 ----
    {
        const float p0 = POT[n * 4 + 0];
        const float* x0r = X0 + n * C;
        const float* qr  = Q + n * C;
        float accZ[12], t[12];

        stageW4(B, g_G0, C * C / 4);
        __syncthreads();
        #pragma unroll
        for (int j = 0; j < 12; j++) t[j] = 0.f;
        #pragma unroll 8
        for (int u = 0; u < C; u++) fma12(t, x0r[u], B + u * C + v0);
        #pragma unroll
        for (int j = 0; j < 12; j++) accZ[j] = p0 * t[j];
        __syncthreads();

        stageW4(B, g_G1, C * C / 4);
        __syncthreads();
        #pragma unroll
        for (int j = 0; j < 12; j++) t[j] = 0.f;
        #pragma unroll 8
        for (int u = 0; u < C; u++) fma12(t, x0r[u], B + u * C + v0);
        #pragma unroll
        for (int j = 0; j < 12; j++) accZ[j] += t[j];
        __syncthreads();

        stageW4(B, g_G2, C * C / 4);
        __syncthreads();
        #pragma unroll
        for (int j = 0; j < 12; j++) t[j] = 0.f;
        #pragma unroll 8
        for (int u = 0; u < C; u++) fma12(t, qr[u], B + u * C + v0);
        float* fr = F + n * C + v0;
        #pragma unroll
        for (int j = 0; j < 12; j++) {
            float pr = accZ[j] + t[j];
            fr[j] = pr * pr;
        }
    }
    __syncthreads();

    // ---- stage 4: MLP norms -> tp_w ----
    stageW4(B,        Wm1, (C * 16) / 4);      // 96x16
    stageW4(B + 1536, Wm2, (16 * 16) / 4);     // 16x16
    stageW4(B + 1792, Wm3, (16 * 16) / 4);     // 16x16
    stageW4(B + 2048, Wm4, (16 * FOURC) / 4);  // 16x384
    __syncthreads();
    {
        const float cst = silu_cst;
        // h1 = cst*silu(norms @ Wm1 * invC)
        #pragma unroll
        for (int idx = tid; idx < TILE * 16; idx += NTHREADS) {
            int nn = idx >> 4, j = idx & 15;
            const float* nr = F + nn * C;
            float s = 0.f;
            #pragma unroll 8
            for (int u = 0; u < C; u++) s = fmaf(nr[u], B[u * 16 + j], s);
            s *= INV_SQRTC;
            H1[idx] = cst * s / (1.0f + expf(-s));
        }
        __syncthreads();
        // h2
        #pragma unroll
        for (int idx = tid; idx < TILE * 16; idx += NTHREADS) {
            int nn = idx >> 4, j = idx & 15;
            float s = 0.f;
            #pragma unroll
            for (int k = 0; k < 16; k++) s = fmaf(H1[nn * 16 + k], B[1536 + k * 16 + j], s);
            s *= 0.25f;
            H2[idx] = cst * s / (1.0f + expf(-s));
        }
        __syncthreads();
        // h3
        #pragma unroll
        for (int idx = tid; idx < TILE * 16; idx += NTHREADS) {
            int nn = idx >> 4, j = idx & 15;
            float s = 0.f;
            #pragma unroll
            for (int k = 0; k < 16; k++) s = fmaf(H2[nn * 16 + k], B[1792 + k * 16 + j], s);
            s *= 0.25f;
            H1[idx] = cst * s / (1.0f + expf(-s));
        }
        __syncthreads();
        // tp_w = h3 @ W_mlp4 * 0.25  -> G (16 x 384)
        for (int nn = 0; nn < TILE; nn++) {
            float h[16];
            #pragma unroll
            for (int k = 0; k < 16; k++) h[k] = H1[nn * 16 + k];
            #pragma unroll
            for (int jj = 0; jj < 3; jj++) {
                int j = tid + jj * NTHREADS;
                float s = 0.f;
                #pragma unroll
                for (int k = 0; k < 16; k++) s = fmaf(h[k], B[2048 + k * FOURC + j], s);
                G[nn * FOURC + j] = s * 0.25f;
            }
        }
    }
    __syncthreads();

    // ---- stage 5: outputs ----
    const float p0  = POT[n * 4 + 0];
    const float p10 = POT[n * 4 + 1], p11v = POT[n * 4 + 2], p12 = POT[n * 4 + 3];
    const float* tpr = G + n * FOURC;   // [w00 | w01 | w10 | w11]
    const float* x0r = X0 + n * C;
    const float* qr  = Q + n * C;

    // 5.1: s_a = (w01*x0) @ W_out1a  (kept in registers)
    float sa[12];
    stageW4(B, Wo1a, C * C / 4);
    __syncthreads();
    {
        #pragma unroll
        for (int j = 0; j < 12; j++) sa[j] = 0.f;
        #pragma unroll 4
        for (int u = 0; u < C; u++) fma12(sa, tpr[C + u] * x0r[u], B + u * C + v0);
    }
    __syncthreads();

    // 5.2: s_b_m = (w10*x1_m) @ W_out1b ; out1[n,v,m] = (p1m*s_a + p0*s_b_m)*norm_out
    stageW4(B, Wo1b, C * C / 4);
    __syncthreads();
    {
        float c0[12], c1[12], c2[12];
        #pragma unroll
        for (int j = 0; j < 12; j++) { c0[j] = 0.f; c1[j] = 0.f; c2[j] = 0.f; }
        const float* x1r0 = X1 + 0 * (TILE * C) + n * C;
        const float* x1r1 = X1 + 1 * (TILE * C) + n * C;
        const float* x1r2 = X1 + 2 * (TILE * C) + n * C;
        #pragma unroll 4
        for (int u = 0; u < C; u++) {
            float w10v = tpr[2 * C + u];
            fma12x3(c0, c1, c2, w10v * x1r0[u], w10v * x1r1[u], w10v * x1r2[u], B + u * C + v0);
        }
        float o[36];
        #pragma unroll
        for (int j = 0; j < 12; j++) {
            float s = sa[j];
            o[j * 3 + 0] = (p10  * s + p0 * c0[j]) * NORM_OUT;
            o[j * 3 + 1] = (p11v * s + p0 * c1[j]) * NORM_OUT;
            o[j * 3 + 2] = (p12  * s + p0 * c2[j]) * NORM_OUT;
        }
        float4* dst = reinterpret_cast<float4*>(out + (size_t)row * FOURC + C + v0 * 3);
        const float4* src = reinterpret_cast<const float4*>(o);
        #pragma unroll
        for (int i = 0; i < 9; i++) dst[i] = src[i];
    }
    __syncthreads();

    // 5.3/5.4: out0 = ( p0*((w00*x0)@W_out0a) + inv_sqrt3*((w11*q)@W_out0b) ) * norm_out
    float o1[12];
    stageW4(B, Wo0a, C * C / 4);
    __syncthreads();
    {
        #pragma unroll
        for (int j = 0; j < 12; j++) o1[j] = 0.f;
        #pragma unroll 4
        for (int u = 0; u < C; u++) fma12(o1, tpr[u] * x0r[u], B + u * C + v0);
    }
    __syncthreads();
    stageW4(B, Wo0b, C * C / 4);
    __syncthreads();
    {
        float o2[12];
        #pragma unroll
        for (int j = 0; j < 12; j++) o2[j] = 0.f;
        #pragma unroll 4
        for (int u = 0; u < C; u++) fma12(o2, tpr[3 * C + u] * qr[u], B + u * C + v0);
        float o[12];
        #pragma unroll
        for (int j = 0; j < 12; j++)
            o[j] = (p0 * o1[j] + o2[j] * INV_SQRT3) * NORM_OUT;
        float4* dst = reinterpret_cast<float4*>(out + (size_t)row * FOURC + v0);
        const float4* src = reinterpret_cast<const float4*>(o);
        #pragma unroll
        for (int i = 0; i < 3; i++) dst[i] = src[i];
    }
}

// ---------------------------------------------------------------------------
extern "C" void kernel_launch(void* const* d_in, const int* in_sizes, int n_in,
                              void* d_out, int out_size)
{
    const float* nf    = (const float*)d_in[0];
    const float* pot   = (const float*)d_in[1];
    const float* Wl1_0 = (const float*)d_in[2];
    const float* Wl1_1 = (const float*)d_in[3];
    const float* Wl2_0 = (const float*)d_in[4];
    const float* bl2_0 = (const float*)d_in[5];
    const float* Wl2_1 = (const float*)d_in[6];
    const float* W00   = (const float*)d_in[7];
    const float* W11   = (const float*)d_in[8];
    const float* Wm1   = (const float*)d_in[9];
    const float* Wm2   = (const float*)d_in[10];
    const float* Wm3   = (const float*)d_in[11];
    const float* Wm4   = (const float*)d_in[12];
    const float* Wo0a  = (const float*)d_in[13];
    const float* Wo0b  = (const float*)d_in[14];
    const float* Wo1a  = (const float*)d_in[15];
    const float* Wo1b  = (const float*)d_in[16];
    float* out = (float*)d_out;

    // SILU_CST: pure constant — replicate the reference quadrature on the host
    // in double precision (matches numpy float64 to ~1e-13 rel).
    double dz = 24.0 / 200000.0;
    double m2 = 0.0;
    const double inv_sqrt2pi = 0.3989422804014326779399460599343818684759;
    for (int i = 0; i <= 200000; i++) {
        double z = -12.0 + i * dz;
        double s = z / (1.0 + exp(-z));
        m2 += s * s * exp(-0.5 * z * z) * inv_sqrt2pi;
    }
    m2 *= dz;
    float silu_cst = (float)(1.0 / sqrt(m2));

    cudaFuncSetAttribute(main_kernel, cudaFuncAttributeMaxDynamicSharedMemorySize, SMEM_BYTES);

    precompute_kernel<<<36, 256>>>(W00, W11, Wl2_0, bl2_0, Wl2_1);
    main_kernel<<<NCTAS, NTHREADS, SMEM_BYTES>>>(nf, pot, Wl1_0, Wl1_1,
                                                 Wm1, Wm2, Wm3, Wm4,
                                                 Wo0a, Wo0b, Wo1a, Wo1b, out, silu_cst);
}

// round 4
// speedup vs baseline: 1.6352x; 1.0449x over previous
#include <cuda_runtime.h>
#include <math.h>

#define C 96
#define FOURC 384
#define NNODES 4096
#define TILE 32
#define NTHREADS 128
#define NCTAS (NNODES / TILE)   // 128

// ---------------- shared memory layout (floats) ----------------
#define OFF_B    0        // 9216 : weight buffer A (96x96)
#define OFF_B2   9216     // 9216 : weight buffer B (96x96) / MLP weights
#define OFF_X0   18432    // 3072 : x0 (32 x 96)
#define OFF_X1   21504    // 9216 : x1 [m][n][u] (3 x 32 x 96)
#define OFF_Q    30720    // 3072 : q  (32 x 96)
#define OFF_G    33792    // 12288: tp_w (32 x 384); F(norms) aliased at base
#define OFF_H1   46080    // 512
#define OFF_H2   46592    // 512
#define OFF_POT  47104    // 128
#define SMEM_FLOATS 47232
#define SMEM_BYTES (SMEM_FLOATS * 4)   // 188928 B -> 1 CTA/SM

// ---------------- device scratch (precomputed, no allocations) ----------------
__device__ __align__(16) float g_G0[C * C];
__device__ __align__(16) float g_G1[C * C];
__device__ __align__(16) float g_G2[C * C];

// ---------------------------------------------------------------------------
// Precompute: collapse C x C x C fctp tensors against rank-1 y-factors.
// ---------------------------------------------------------------------------
__global__ void precompute_kernel(const float* __restrict__ W00,
                                  const float* __restrict__ W11,
                                  const float* __restrict__ Wl2_0,
                                  const float* __restrict__ bl2_0,
                                  const float* __restrict__ Wl2_1)
{
    int idx = blockIdx.x * 256 + threadIdx.x;   // (u, w), w fastest
    if (idx >= C * C) return;
    int u = idx / C;
    int w = idx - u * C;
    const float* p00 = W00 + u * C * C + w;
    const float* p11 = W11 + u * C * C + w;
    float a = 0.f, b = 0.f, c = 0.f;
    #pragma unroll 4
    for (int v = 0; v < C; v++) {
        float e00 = p00[v * C];
        float e11 = p11[v * C];
        a = fmaf(Wl2_0[v], e00, a);
        b = fmaf(bl2_0[v], e00, b);
        c = fmaf(Wl2_1[v], e11, c);
    }
    const float inv_s2 = 1.0f / sqrtf(2.0f * C * C);
    const float inv_s3 = 1.0f / sqrtf(3.0f);
    g_G0[idx] = a * inv_s2;
    g_G1[idx] = b * inv_s2;
    g_G2[idx] = c * inv_s2 * inv_s3;
}

// ---------------------------------------------------------------------------
// Helpers
// ---------------------------------------------------------------------------
__device__ __forceinline__ void stageW4(float* dst, const float* __restrict__ src, int n4)
{
    float4* d = reinterpret_cast<float4*>(dst);
    const float4* s = reinterpret_cast<const float4*>(src);
    for (int i = threadIdx.x; i < n4; i += NTHREADS) d[i] = s[i];
}

__device__ __forceinline__ void loadw12(float w[12], const float* wrow)
{
    *reinterpret_cast<float4*>(w)     = *reinterpret_cast<const float4*>(wrow);
    *reinterpret_cast<float4*>(w + 4) = *reinterpret_cast<const float4*>(wrow + 4);
    *reinterpret_cast<float4*>(w + 8) = *reinterpret_cast<const float4*>(wrow + 8);
}

// one weight row feeds two accumulator sets (two nodes)
__device__ __forceinline__ void fma12_dual(float a[12], float b[12],
                                           float sa, float sb, const float* wrow)
{
    float w[12];
    loadw12(w, wrow);
    #pragma unroll
    for (int j = 0; j < 12; j++) {
        a[j] = fmaf(sa, w[j], a[j]);
        b[j] = fmaf(sb, w[j], b[j]);
    }
}

// one weight row feeds six accumulator sets (3 m-components x 2 nodes)
__device__ __forceinline__ void fma12_hex(float c0[12], float c1[12], float c2[12],
                                          float c3[12], float c4[12], float c5[12],
                                          float s0, float s1, float s2,
                                          float s3, float s4, float s5,
                                          const float* wrow)
{
    float w[12];
    loadw12(w, wrow);
    #pragma unroll
    for (int j = 0; j < 12; j++) {
        c0[j] = fmaf(s0, w[j], c0[j]);
        c1[j] = fmaf(s1, w[j], c1[j]);
        c2[j] = fmaf(s2, w[j], c2[j]);
        c3[j] = fmaf(s3, w[j], c3[j]);
        c4[j] = fmaf(s4, w[j], c4[j]);
        c5[j] = fmaf(s5, w[j], c5[j]);
    }
}

// ---------------------------------------------------------------------------
// Fused main kernel: 1 CTA = 32 nodes; each thread owns 2 nodes x 12 cols.
// n-group g = tid>>3 (nodes g and g+16), v0 = (tid&7)*12.
// ---------------------------------------------------------------------------
__global__ void __launch_bounds__(NTHREADS, 1)
main_kernel(const float* __restrict__ nf, const float* __restrict__ pot,
            const float* __restrict__ Wl1_0, const float* __restrict__ Wl1_1,
            const float* __restrict__ Wm1, const float* __restrict__ Wm2,
            const float* __restrict__ Wm3, const float* __restrict__ Wm4,
            const float* __restrict__ Wo0a, const float* __restrict__ Wo0b,
            const float* __restrict__ Wo1a, const float* __restrict__ Wo1b,
            float* __restrict__ out, float silu_cst)
{
    extern __shared__ __align__(16) float sm[];
    float* B   = sm + OFF_B;
    float* B2  = sm + OFF_B2;
    float* X0  = sm + OFF_X0;
    float* X1  = sm + OFF_X1;
    float* Q   = sm + OFF_Q;
    float* G   = sm + OFF_G;     // F (norms) aliased at G base
    float* F   = sm + OFF_G;
    float* H1  = sm + OFF_H1;
    float* H2  = sm + OFF_H2;
    float* POT = sm + OFF_POT;

    const float INV_SQRTC = 1.0f / sqrtf((float)C);
    const float INV_SQRT3 = 1.0f / sqrtf(3.0f);
    const float NORM_OUT  = 1.0f / sqrtf(2.0f * C);

    const int tid  = threadIdx.x;
    const int base = blockIdx.x * TILE;
    const int g    = tid >> 3;          // 0..15
    const int na   = g, nbn = g + 16;   // two nodes per thread
    const int v0   = (tid & 7) * 12;
    const int rowa = base + na;
    const int rowb = base + nbn;

    // ---- staging block 1: pot + Wl1_0 + Wl1_1 ----
    POT[tid] = pot[base * 4 + tid];     // TILE*4 == NTHREADS
    stageW4(B,  Wl1_0, C * C / 4);
    stageW4(B2, Wl1_1, C * C / 4);
    __syncthreads();

    // ---- stage 1: x0 = nf[:, :C] @ Wl1_0 * invC (both nodes) ----
    {
        float aa[12], ab[12];
        #pragma unroll
        for (int j = 0; j < 12; j++) { aa[j] = 0.f; ab[j] = 0.f; }
        const float* ra = nf + (size_t)rowa * FOURC;
        const float* rb = nf + (size_t)rowb * FOURC;
        #pragma unroll 1
        for (int u = 0; u < C; u += 4) {
            float4 a4 = *reinterpret_cast<const float4*>(ra + u);
            float4 b4 = *reinterpret_cast<const float4*>(rb + u);
            fma12_dual(aa, ab, a4.x, b4.x, B + (u + 0) * C + v0);
            fma12_dual(aa, ab, a4.y, b4.y, B + (u + 1) * C + v0);
            fma12_dual(aa, ab, a4.z, b4.z, B + (u + 2) * C + v0);
            fma12_dual(aa, ab, a4.w, b4.w, B + (u + 3) * C + v0);
        }
        float* xra = X0 + na * C + v0;
        float* xrb = X0 + nbn * C + v0;
        #pragma unroll
        for (int j = 0; j < 12; j++) { xra[j] = aa[j] * INV_SQRTC; xrb[j] = ab[j] * INV_SQRTC; }
    }

    // ---- stage 2: x1_m = nf1_m @ Wl1_1 * invC (3 m x 2 nodes); q = sum_m x1_m p1_m ----
    {
        float c0[12], c1[12], c2[12], c3[12], c4[12], c5[12];
        #pragma unroll
        for (int j = 0; j < 12; j++) { c0[j]=0.f; c1[j]=0.f; c2[j]=0.f; c3[j]=0.f; c4[j]=0.f; c5[j]=0.f; }
        const float* ra = nf + (size_t)rowa * FOURC + C;
        const float* rb = nf + (size_t)rowb * FOURC + C;
        #pragma unroll 1
        for (int u = 0; u < C; u += 4) {
            float4 a0 = *reinterpret_cast<const float4*>(ra + u * 3);
            float4 a1 = *reinterpret_cast<const float4*>(ra + u * 3 + 4);
            float4 a2 = *reinterpret_cast<const float4*>(ra + u * 3 + 8);
            float4 b0 = *reinterpret_cast<const float4*>(rb + u * 3);
            float4 b1 = *reinterpret_cast<const float4*>(rb + u * 3 + 4);
            float4 b2 = *reinterpret_cast<const float4*>(rb + u * 3 + 8);
            fma12_hex(c0,c1,c2,c3,c4,c5, a0.x,a0.y,a0.z, b0.x,b0.y,b0.z, B2 + (u + 0) * C + v0);
            fma12_hex(c0,c1,c2,c3,c4,c5, a0.w,a1.x,a1.y, b0.w,b1.x,b1.y, B2 + (u + 1) * C + v0);
            fma12_hex(c0,c1,c2,c3,c4,c5, a1.z,a1.w,a2.x, b1.z,b1.w,b2.x, B2 + (u + 2) * C + v0);
            fma12_hex(c0,c1,c2,c3,c4,c5, a2.y,a2.z,a2.w, b2.y,b2.z,b2.w, B2 + (u + 3) * C + v0);
        }
        float pa1 = POT[na * 4 + 1], pa2 = POT[na * 4 + 2], pa3 = POT[na * 4 + 3];
        float pb1 = POT[nbn * 4 + 1], pb2 = POT[nbn * 4 + 2], pb3 = POT[nbn * 4 + 3];
        float* x1a0 = X1 + 0 * (TILE * C) + na * C + v0;
        float* x1a1 = X1 + 1 * (TILE * C) + na * C + v0;
        float* x1a2 = X1 + 2 * (TILE * C) + na * C + v0;
        float* x1b0 = X1 + 0 * (TILE * C) + nbn * C + v0;
        float* x1b1 = X1 + 1 * (TILE * C) + nbn * C + v0;
        float* x1b2 = X1 + 2 * (TILE * C) + nbn * C + v0;
        float* qa   = Q + na * C + v0;
        float* qb   = Q + nbn * C + v0;
        #pragma unroll
        for (int j = 0; j < 12; j++) {
            float e0 = c0[j] * INV_SQRTC, e1 = c1[j] * INV_SQRTC, e2 = c2[j] * INV_SQRTC;
            float f0 = c3[j] * INV_SQRTC, f1 = c4[j] * INV_SQRTC, f2 = c5[j] * INV_SQRTC;
            x1a0[j] = e0; x1a1[j] = e1; x1a2[j] = e2;
            x1b0[j] = f0; x1b1[j] = f1; x1b2[j] = f2;
            qa[j] = e0 * pa1 + e1 * pa2 + e2 * pa3;
            qb[j] = f0 * pb1 + f1 * pb2 + f2 * pb3;
        }
    }
    __syncthreads();

    // ---- staging block 2: G0 + G1 ----
    stageW4(B,  g_G0, C * C / 4);
    stageW4(B2, g_G1, C * C / 4);
    __syncthreads();

    // ---- stage 3a: s0 = x0@G0, s1 = x0@G1 (both nodes) ----
    float za[12], zb[12];
    {
        float s0a[12], s1a[12], s0b[12], s1b[12];
        #pragma unroll
        for (int j = 0; j < 12; j++) { s0a[j]=0.f; s1a[j]=0.f; s0b[j]=0.f; s1b[j]=0.f; }
        const float* xa = X0 + na * C;
        const float* xb = X0 + nbn * C;
        #pragma unroll 2
        for (int u = 0; u < C; u++) {
            float av = xa[u], bv = xb[u];
            fma12_dual(s0a, s0b, av, bv, B  + u * C + v0);
            fma12_dual(s1a, s1b, av, bv, B2 + u * C + v0);
        }
        float p0a = POT[na * 4 + 0], p0b = POT[nbn * 4 + 0];
        #pragma unroll
        for (int j = 0; j < 12; j++) {
            za[j] = p0a * s0a[j] + s1a[j];
            zb[j] = p0b * s0b[j] + s1b[j];
        }
    }
    __syncthreads();

    // ---- staging block 3: G2 + all MLP weights (into B2) ----
    stageW4(B, g_G2, C * C / 4);
    stageW4(B2,        Wm1, (C * 16) / 4);
    stageW4(B2 + 1536, Wm2, (16 * 16) / 4);
    stageW4(B2 + 1792, Wm3, (16 * 16) / 4);
    stageW4(B2 + 2048, Wm4, (16 * FOURC) / 4);
    __syncthreads();

    // ---- stage 3b: z += q@G2 ; F = z^2 ----
    {
        float ta[12], tb[12];
        #pragma unroll
        for (int j = 0; j < 12; j++) { ta[j] = 0.f; tb[j] = 0.f; }
        const float* qa = Q + na * C;
        const float* qb = Q + nbn * C;
        #pragma unroll 2
        for (int u = 0; u < C; u++)
            fma12_dual(ta, tb, qa[u], qb[u], B + u * C + v0);
        float* fa = F + na * C + v0;
        float* fb = F + nbn * C + v0;
        #pragma unroll
        for (int j = 0; j < 12; j++) {
            float pa = za[j] + ta[j];
            float pb = zb[j] + tb[j];
            fa[j] = pa * pa;
            fb[j] = pb * pb;
        }
    }
    __syncthreads();

    // ---- stage 4: MLP norms -> tp_w ----
    {
        const float cst = silu_cst;
        #pragma unroll
        for (int idx = tid; idx < TILE * 16; idx += NTHREADS) {
            int nn = idx >> 4, j = idx & 15;
            const float* nr = F + nn * C;
            float s = 0.f;
            #pragma unroll 8
            for (int u = 0; u < C; u++) s = fmaf(nr[u], B2[u * 16 + j], s);
            s *= INV_SQRTC;
            H1[idx] = cst * s / (1.0f + expf(-s));
        }
        __syncthreads();
        #pragma unroll
        for (int idx = tid; idx < TILE * 16; idx += NTHREADS) {
            int nn = idx >> 4, j = idx & 15;
            float s = 0.f;
            #pragma unroll
            for (int k = 0; k < 16; k++) s = fmaf(H1[nn * 16 + k], B2[1536 + k * 16 + j], s);
            s *= 0.25f;
            H2[idx] = cst * s / (1.0f + expf(-s));
        }
        __syncthreads();
        #pragma unroll
        for (int idx = tid; idx < TILE * 16; idx += NTHREADS) {
            int nn = idx >> 4, j = idx & 15;
            float s = 0.f;
            #pragma unroll
            for (int k = 0; k < 16; k++) s = fmaf(H2[nn * 16 + k], B2[1792 + k * 16 + j], s);
            s *= 0.25f;
            H1[idx] = cst * s / (1.0f + expf(-s));
        }
        __syncthreads();
        // tp_w = h3 @ Wm4 * 0.25  -> G (32 x 384) (overwrites F region; F is dead)
        for (int nn = 0; nn < TILE; nn++) {
            float h[16];
            #pragma unroll
            for (int k = 0; k < 16; k++) h[k] = H1[nn * 16 + k];
            #pragma unroll
            for (int jj = 0; jj < 3; jj++) {
                int j = tid + jj * NTHREADS;
                float s = 0.f;
                #pragma unroll
                for (int k = 0; k < 16; k++) s = fmaf(h[k], B2[2048 + k * FOURC + j], s);
                G[nn * FOURC + j] = s * 0.25f;
            }
        }
    }
    __syncthreads();

    // ---- staging block 4: Wo1a + Wo1b ----
    stageW4(B,  Wo1a, C * C / 4);
    stageW4(B2, Wo1b, C * C / 4);
    __syncthreads();

    const float p0a = POT[na * 4 + 0],  p0b = POT[nbn * 4 + 0];
    const float pa1 = POT[na * 4 + 1],  pa2 = POT[na * 4 + 2],  pa3 = POT[na * 4 + 3];
    const float pb1 = POT[nbn * 4 + 1], pb2 = POT[nbn * 4 + 2], pb3 = POT[nbn * 4 + 3];
    const float* tpa = G + na * FOURC;    // [w00 | w01 | w10 | w11]
    const float* tpb = G + nbn * FOURC;
    const float* xa  = X0 + na * C;
    const float* xb  = X0 + nbn * C;
    const float* qa  = Q + na * C;
    const float* qb  = Q + nbn * C;

    // 5.1: s_a = (w01*x0) @ Wo1a  (registers, both nodes)
    float saa[12], sab[12];
    {
        #pragma unroll
        for (int j = 0; j < 12; j++) { saa[j] = 0.f; sab[j] = 0.f; }
        #pragma unroll 2
        for (int u = 0; u < C; u++)
            fma12_dual(saa, sab, tpa[C + u] * xa[u], tpb[C + u] * xb[u], B + u * C + v0);
    }

    // 5.2: s_b_m = (w10*x1_m) @ Wo1b ; out1 = (p1m*s_a + p0*s_b_m)*norm_out
    {
        float c0[12], c1[12], c2[12], c3[12], c4[12], c5[12];
        #pragma unroll
        for (int j = 0; j < 12; j++) { c0[j]=0.f; c1[j]=0.f; c2[j]=0.f; c3[j]=0.f; c4[j]=0.f; c5[j]=0.f; }
        const float* x1a0 = X1 + 0 * (TILE * C) + na * C;
        const float* x1a1 = X1 + 1 * (TILE * C) + na * C;
        const float* x1a2 = X1 + 2 * (TILE * C) + na * C;
        const float* x1b0 = X1 + 0 * (TILE * C) + nbn * C;
        const float* x1b1 = X1 + 1 * (TILE * C) + nbn * C;
        const float* x1b2 = X1 + 2 * (TILE * C) + nbn * C;
        #pragma unroll 2
        for (int u = 0; u < C; u++) {
            float wa = tpa[2 * C + u], wb = tpb[2 * C + u];
            fma12_hex(c0,c1,c2,c3,c4,c5,
                      wa * x1a0[u], wa * x1a1[u], wa * x1a2[u],
                      wb * x1b0[u], wb * x1b1[u], wb * x1b2[u],
                      B2 + u * C + v0);
        }
        float oa[36], ob[36];
        #pragma unroll
        for (int j = 0; j < 12; j++) {
            float sa = saa[j], sb = sab[j];
            oa[j*3+0] = (pa1 * sa + p0a * c0[j]) * NORM_OUT;
            oa[j*3+1] = (pa2 * sa + p0a * c1[j]) * NORM_OUT;
            oa[j*3+2] = (pa3 * sa + p0a * c2[j]) * NORM_OUT;
            ob[j*3+0] = (pb1 * sb + p0b * c3[j]) * NORM_OUT;
            ob[j*3+1] = (pb2 * sb + p0b * c4[j]) * NORM_OUT;
            ob[j*3+2] = (pb3 * sb + p0b * c5[j]) * NORM_OUT;
        }
        float4* da = reinterpret_cast<float4*>(out + (size_t)rowa * FOURC + C + v0 * 3);
        float4* db = reinterpret_cast<float4*>(out + (size_t)rowb * FOURC + C + v0 * 3);
        const float4* sa4 = reinterpret_cast<const float4*>(oa);
        const float4* sb4 = reinterpret_cast<const float4*>(ob);
        #pragma unroll
        for (int i = 0; i < 9; i++) { da[i] = sa4[i]; db[i] = sb4[i]; }
    }
    __syncthreads();

    // ---- staging block 5: Wo0a + Wo0b ----
    stageW4(B,  Wo0a, C * C / 4);
    stageW4(B2, Wo0b, C * C / 4);
    __syncthreads();

    // 5.3: out0 = ( p0*((w00*x0)@Wo0a) + inv_sqrt3*((w11*q)@Wo0b) ) * norm_out
    {
        float o1a[12], o1b[12], o2a[12], o2b[12];
        #pragma unroll
        for (int j = 0; j < 12; j++) { o1a[j]=0.f; o1b[j]=0.f; o2a[j]=0.f; o2b[j]=0.f; }
        #pragma unroll 2
        for (int u = 0; u < C; u++) {
            fma12_dual(o1a, o1b, tpa[u] * xa[u],          tpb[u] * xb[u],          B  + u * C + v0);
            fma12_dual(o2a, o2b, tpa[3 * C + u] * qa[u],  tpb[3 * C + u] * qb[u],  B2 + u * C + v0);
        }
        float oa[12], ob[12];
        #pragma unroll
        for (int j = 0; j < 12; j++) {
            oa[j] = (p0a * o1a[j] + o2a[j] * INV_SQRT3) * NORM_OUT;
            ob[j] = (p0b * o1b[j] + o2b[j] * INV_SQRT3) * NORM_OUT;
        }
        float4* da = reinterpret_cast<float4*>(out + (size_t)rowa * FOURC + v0);
        float4* db = reinterpret_cast<float4*>(out + (size_t)rowb * FOURC + v0);
        const float4* sa4 = reinterpret_cast<const float4*>(oa);
        const float4* sb4 = reinterpret_cast<const float4*>(ob);
        #pragma unroll
        for (int i = 0; i < 3; i++) { da[i] = sa4[i]; db[i] = sb4[i]; }
    }
}

// ---------------------------------------------------------------------------
extern "C" void kernel_launch(void* const* d_in, const int* in_sizes, int n_in,
                              void* d_out, int out_size)
{
    const float* nf    = (const float*)d_in[0];
    const float* pot   = (const float*)d_in[1];
    const float* Wl1_0 = (const float*)d_in[2];
    const float* Wl1_1 = (const float*)d_in[3];
    const float* Wl2_0 = (const float*)d_in[4];
    const float* bl2_0 = (const float*)d_in[5];
    const float* Wl2_1 = (const float*)d_in[6];
    const float* W00   = (const float*)d_in[7];
    const float* W11   = (const float*)d_in[8];
    const float* Wm1   = (const float*)d_in[9];
    const float* Wm2   = (const float*)d_in[10];
    const float* Wm3   = (const float*)d_in[11];
    const float* Wm4   = (const float*)d_in[12];
    const float* Wo0a  = (const float*)d_in[13];
    const float* Wo0b  = (const float*)d_in[14];
    const float* Wo1a  = (const float*)d_in[15];
    const float* Wo1b  = (const float*)d_in[16];
    float* out = (float*)d_out;

    // SILU_CST: input-independent — replicate reference quadrature on host (f64).
    double dz = 24.0 / 200000.0;
    double m2 = 0.0;
    const double inv_sqrt2pi = 0.3989422804014326779399460599343818684759;
    for (int i = 0; i <= 200000; i++) {
        double z = -12.0 + i * dz;
        double s = z / (1.0 + exp(-z));
        m2 += s * s * exp(-0.5 * z * z) * inv_sqrt2pi;
    }
    m2 *= dz;
    float silu_cst = (float)(1.0 / sqrt(m2));

    cudaFuncSetAttribute(main_kernel, cudaFuncAttributeMaxDynamicSharedMemorySize, SMEM_BYTES);

    precompute_kernel<<<36, 256>>>(W00, W11, Wl2_0, bl2_0, Wl2_1);
    main_kernel<<<NCTAS, NTHREADS, SMEM_BYTES>>>(nf, pot, Wl1_0, Wl1_1,
                                                 Wm1, Wm2, Wm3, Wm4,
                                                 Wo0a, Wo0b, Wo1a, Wo1b, out, silu_cst);
}